// round 5
// baseline (speedup 1.0000x reference)
#include <cuda_runtime.h>

#define THR 1.2f

// [tb][pixel][half] 32-bit channel spike masks from layer 1 (4 MB)
__device__ unsigned g_mask[512 * 1024 * 2];
// per-block FC partial sums: 1024 blocks x 10 classes
__device__ float g_part[1024 * 10];

// ---------------------------------------------------------------------------
// Kernel 1: conv1 (3->64, 3x3, pad 1) + LIF threshold -> channel bitmasks
// Grid: 512 blocks (one per (t,b) image), 256 threads.
// ---------------------------------------------------------------------------
__global__ __launch_bounds__(256) void k1_conv1(const float* __restrict__ x,
                                                const float* __restrict__ w1,
                                                const float* __restrict__ b1) {
    __shared__ float xs[3 * 34 * 34];   // input with zero halo
    __shared__ float ws[64 * 27];
    __shared__ float bs[64];

    const int tb  = blockIdx.x;
    const int tid = threadIdx.x;

    for (int i = tid; i < 64 * 27; i += 256) ws[i] = w1[i];
    if (tid < 64) bs[tid] = b1[tid];

    const float* xin = x + tb * 3 * 1024;
    for (int i = tid; i < 3 * 34 * 34; i += 256) {
        int cin = i / 1156, rem = i - cin * 1156;
        int yy = rem / 34, xx = rem - yy * 34;
        int gy = yy - 1, gx = xx - 1;
        float v = 0.f;
        if (gy >= 0 && gy < 32 && gx >= 0 && gx < 32)
            v = xin[cin * 1024 + gy * 32 + gx];
        xs[i] = v;
    }
    __syncthreads();

    const int wid  = tid >> 5;
    const int lane = tid & 31;
    const int half = wid & 1;           // which 32-channel group this warp owns
    const int c    = half * 32 + lane;  // lane -> output channel

    float wr[27];
#pragma unroll
    for (int k = 0; k < 27; k++) wr[k] = ws[c * 27 + k];  // stride 27: conflict-free
    const float bias = bs[c];

    for (int p = (wid >> 1); p < 1024; p += 4) {
        const int y = p >> 5, xcol = p & 31;
        const float* xp = xs + y * 34 + xcol;
        float s = 0.f;
#pragma unroll
        for (int cin = 0; cin < 3; cin++)
#pragma unroll
            for (int ky = 0; ky < 3; ky++)
#pragma unroll
                for (int kx = 0; kx < 3; kx++)
                    s += wr[cin * 9 + ky * 3 + kx] * xp[cin * 1156 + ky * 34 + kx];
        unsigned bal = __ballot_sync(0xffffffffu, (s + bias) >= THR);
        if (lane == 0) g_mask[(tb * 1024 + p) * 2 + half] = bal;
    }
}

// Predicated packed-f32x2 accumulate: one predicate feeds 8 channel accs (4 pairs).
#define PADD4X2(cond, a0, a1, a2, a3, w0, w1, w2, w3)                     \
    asm("{\n\t.reg .pred p;\n\tsetp.ne.u32 p, %8, 0;\n\t"                 \
        "@p add.rn.f32x2 %0, %0, %4;\n\t"                                 \
        "@p add.rn.f32x2 %1, %1, %5;\n\t"                                 \
        "@p add.rn.f32x2 %2, %2, %6;\n\t"                                 \
        "@p add.rn.f32x2 %3, %3, %7;\n\t}"                                \
        : "+l"(a0), "+l"(a1), "+l"(a2), "+l"(a3)                          \
        : "l"(w0), "l"(w1), "l"(w2), "l"(w3), "r"(cond))

// ---------------------------------------------------------------------------
// Kernel 2: conv2 (64->64, binary input) + LIF + count over t + fused FC.
// Grid: (8 row-strips, 64 batch, 2 co-halves), 128 threads = 4 rows x 32 cols.
// Each thread owns one pixel; accumulates 8 output channels x 8 timesteps
// via predicated weight adds, thresholds -> spike count, multiplies by wfc.
// ---------------------------------------------------------------------------
__global__ __launch_bounds__(128) void k2_conv2(const float* __restrict__ w2,
                                                const float* __restrict__ b2,
                                                const float* __restrict__ wfc) {
    __shared__ uint2 sm_mask[8][6][34];      // [t][strip row + halo][x + halo]
    __shared__ float sm_w[9 * 64 * 8];       // [pos][cin][co8]
    __shared__ float sm_b[8];
    __shared__ float sm_red[4 * 10];

    const int sy  = blockIdx.x;              // row strip (4 rows each)
    const int b   = blockIdx.y;
    const int zc  = blockIdx.z;              // 0/1 -> output channels [0,32) / [32,64)
    const int tid = threadIdx.x;
    const int ry  = tid >> 5;                // row within strip
    const int xc  = tid & 31;

    // Stage spike masks for this (b, strip) incl. halo, all 8 timesteps.
    for (int i = tid; i < 8 * 6 * 34; i += 128) {
        int t = i / 204, rem = i - t * 204;
        int r = rem / 34, xi = rem - r * 34;
        int gy = sy * 4 - 1 + r;
        int gx = xi - 1;
        uint2 v = make_uint2(0u, 0u);
        if (gy >= 0 && gy < 32 && gx >= 0 && gx < 32) {
            const uint2* gm = (const uint2*)g_mask;
            v = gm[(t * 64 + b) * 1024 + gy * 32 + gx];
        }
        sm_mask[t][r][xi] = v;
    }

    float outacc[10];
#pragma unroll
    for (int o = 0; o < 10; o++) outacc[o] = 0.f;

    const int gp = (sy * 4 + ry) * 32 + xc;  // global pixel index

    for (int chunk = 0; chunk < 4; chunk++) {
        const int coBase = zc * 32 + chunk * 8;
        __syncthreads();
        // sm_w[(pos*64+cin)*8 + co8] = w2[(coBase+co8)*576 + cin*9 + pos]
        for (int i = tid; i < 4608; i += 128) {
            int co8 = i / 576;               // coalesced over 'rest'
            int rest = i - co8 * 576;        // = cin*9 + pos
            int cin = rest / 9, pos = rest - cin * 9;
            sm_w[(pos * 64 + cin) * 8 + co8] = w2[(coBase + co8) * 576 + rest];
        }
        if (tid < 8) sm_b[tid] = b2[coBase + tid];
        __syncthreads();

        unsigned long long acc[8][4];        // [t][channel pair], packed f32x2
#pragma unroll
        for (int t = 0; t < 8; t++) {
#pragma unroll
            for (int q = 0; q < 4; q++) acc[t][q] = 0ull;
        }

#pragma unroll 1
        for (int dy = 0; dy < 3; dy++) {
#pragma unroll 1
            for (int dx = 0; dx < 3; dx++) {
                const int pos = dy * 3 + dx;
                unsigned mx[8], my[8];
#pragma unroll
                for (int t = 0; t < 8; t++) {
                    uint2 m = sm_mask[t][ry + dy][xc + dx];
                    mx[t] = m.x; my[t] = m.y;
                }
                const ulonglong2* swp = (const ulonglong2*)sm_w + pos * 64 * 2;
#pragma unroll
                for (int half = 0; half < 2; half++) {
#pragma unroll 1
                    for (int cb = 0; cb < 4; cb++) {
                        const int sh = cb * 8;
                        unsigned msh[8];
#pragma unroll
                        for (int t = 0; t < 8; t++)
                            msh[t] = (half ? my[t] : mx[t]) >> sh;
                        const ulonglong2* wp = swp + (half * 32 + cb * 8) * 2;
#pragma unroll
                        for (int j = 0; j < 8; j++) {
                            ulonglong2 wA = wp[j * 2];      // co 0..3 (pairs)
                            ulonglong2 wB = wp[j * 2 + 1];  // co 4..7
#pragma unroll
                            for (int t = 0; t < 8; t++) {
                                unsigned cond = msh[t] & (1u << j);
                                PADD4X2(cond,
                                        acc[t][0], acc[t][1], acc[t][2], acc[t][3],
                                        wA.x, wA.y, wB.x, wB.y);
                            }
                        }
                    }
                }
            }
        }

        // threshold -> spike count over t, fold into FC
#pragma unroll
        for (int jp = 0; jp < 4; jp++) {
            const float bias0 = sm_b[jp * 2];
            const float bias1 = sm_b[jp * 2 + 1];
            float cnt0 = 0.f, cnt1 = 0.f;
#pragma unroll
            for (int t = 0; t < 8; t++) {
                float lo, hi;
                asm("mov.b64 {%0,%1}, %2;" : "=f"(lo), "=f"(hi) : "l"(acc[t][jp]));
                cnt0 += ((lo + bias0) >= THR) ? 1.f : 0.f;
                cnt1 += ((hi + bias1) >= THR) ? 1.f : 0.f;
            }
            const int fi0 = (coBase + jp * 2) * 1024 + gp;
            const int fi1 = fi0 + 1024;
#pragma unroll
            for (int o = 0; o < 10; o++)
                outacc[o] += cnt0 * __ldg(&wfc[o * 65536 + fi0])
                           + cnt1 * __ldg(&wfc[o * 65536 + fi1]);
        }
    }

    // block reduction of the 10 partial class sums
    const int lane = tid & 31, wid = tid >> 5;
#pragma unroll
    for (int o = 0; o < 10; o++) {
        float v = outacc[o];
        v += __shfl_down_sync(0xffffffffu, v, 16);
        v += __shfl_down_sync(0xffffffffu, v, 8);
        v += __shfl_down_sync(0xffffffffu, v, 4);
        v += __shfl_down_sync(0xffffffffu, v, 2);
        v += __shfl_down_sync(0xffffffffu, v, 1);
        if (lane == 0) sm_red[wid * 10 + o] = v;
    }
    __syncthreads();
    if (tid < 10) {
        float s = sm_red[tid] + sm_red[10 + tid] + sm_red[20 + tid] + sm_red[30 + tid];
        const int blockLin = (b * 8 + sy) * 2 + zc;  // = b*16 + sy*2 + zc
        g_part[blockLin * 10 + tid] = s;
    }
}

// ---------------------------------------------------------------------------
// Kernel 3: deterministic final reduction: out[b][o] = 8*bfc[o] + sum(parts)
// ---------------------------------------------------------------------------
__global__ void k3_final(const float* __restrict__ bfc, float* __restrict__ out) {
    const int tid = threadIdx.x;
    if (tid < 640) {
        const int b = tid / 10, o = tid - b * 10;
        float s = 8.f * bfc[o];
#pragma unroll
        for (int k = 0; k < 16; k++) s += g_part[(b * 16 + k) * 10 + o];
        out[tid] = s;
    }
}

extern "C" void kernel_launch(void* const* d_in, const int* in_sizes, int n_in,
                              void* d_out, int out_size) {
    const float* x   = (const float*)d_in[0];  // [8,64,3,32,32]
    const float* w1  = (const float*)d_in[1];  // [64,3,3,3]
    const float* b1  = (const float*)d_in[2];  // [64]
    const float* w2  = (const float*)d_in[3];  // [64,64,3,3]
    const float* b2  = (const float*)d_in[4];  // [64]
    const float* wfc = (const float*)d_in[5];  // [10, 65536]
    const float* bfc = (const float*)d_in[6];  // [10]
    float* out = (float*)d_out;                // [64,10]

    k1_conv1<<<512, 256>>>(x, w1, b1);
    k2_conv2<<<dim3(8, 64, 2), 128>>>(w2, b2, wfc);
    k3_final<<<1, 640>>>(bfc, out);
}

// round 6
// speedup vs baseline: 1.5534x; 1.5534x over previous
#include <cuda_runtime.h>

#define THR 1.2f

// [tb][pixel][half] 32-bit channel spike masks from layer 1 (4 MB)
__device__ unsigned g_mask[512 * 1024 * 2];
// per-block FC partial sums: 1024 blocks x 10 classes
__device__ float g_part[1024 * 10];

// ---------------------------------------------------------------------------
// Kernel 1: conv1 (3->64, 3x3, pad 1) + LIF threshold -> channel bitmasks
// Grid: 512 blocks (one per (t,b) image), 256 threads.
// 3 independent accumulator chains (one per cin) to break the FFMA RAW chain.
// ---------------------------------------------------------------------------
__global__ __launch_bounds__(256) void k1_conv1(const float* __restrict__ x,
                                                const float* __restrict__ w1,
                                                const float* __restrict__ b1) {
    __shared__ float xs[3 * 34 * 34];   // input with zero halo
    __shared__ float ws[64 * 27];
    __shared__ float bs[64];

    const int tb  = blockIdx.x;
    const int tid = threadIdx.x;

    for (int i = tid; i < 64 * 27; i += 256) ws[i] = w1[i];
    if (tid < 64) bs[tid] = b1[tid];

    const float* xin = x + tb * 3 * 1024;
    for (int i = tid; i < 3 * 34 * 34; i += 256) {
        int cin = i / 1156, rem = i - cin * 1156;
        int yy = rem / 34, xx = rem - yy * 34;
        int gy = yy - 1, gx = xx - 1;
        float v = 0.f;
        if (gy >= 0 && gy < 32 && gx >= 0 && gx < 32)
            v = xin[cin * 1024 + gy * 32 + gx];
        xs[i] = v;
    }
    __syncthreads();

    const int wid  = tid >> 5;
    const int lane = tid & 31;
    const int half = wid & 1;           // which 32-channel group this warp owns
    const int c    = half * 32 + lane;  // lane -> output channel

    float wr[27];
#pragma unroll
    for (int k = 0; k < 27; k++) wr[k] = ws[c * 27 + k];  // stride 27: conflict-free
    const float bias = bs[c];

#pragma unroll 2
    for (int p = (wid >> 1); p < 1024; p += 4) {
        const int y = p >> 5, xcol = p & 31;
        const float* xp = xs + y * 34 + xcol;
        float s0 = 0.f, s1 = 0.f, s2 = 0.f;
#pragma unroll
        for (int k = 0; k < 9; k++) {
            const int ky = k / 3, kx = k - ky * 3;
            s0 += wr[k]      * xp[ky * 34 + kx];
            s1 += wr[9 + k]  * xp[1156 + ky * 34 + kx];
            s2 += wr[18 + k] * xp[2312 + ky * 34 + kx];
        }
        unsigned bal = __ballot_sync(0xffffffffu, (s0 + s1 + s2 + bias) >= THR);
        if (lane == 0) g_mask[(tb * 1024 + p) * 2 + half] = bal;
    }
}

// 4 packed-f32x2 FMAs: acc_pair += w_pair * {s,s}  (s = 0.0 or 1.0)
#define FFMA4X2(a0, a1, a2, a3, w0, w1, w2, w3, s2)        \
    asm("fma.rn.f32x2 %0, %4, %8, %0;\n\t"                 \
        "fma.rn.f32x2 %1, %5, %8, %1;\n\t"                 \
        "fma.rn.f32x2 %2, %6, %8, %2;\n\t"                 \
        "fma.rn.f32x2 %3, %7, %8, %3;"                     \
        : "+l"(a0), "+l"(a1), "+l"(a2), "+l"(a3)           \
        : "l"(w0), "l"(w1), "l"(w2), "l"(w3), "l"(s2))

// ---------------------------------------------------------------------------
// Kernel 2: conv2 (64->64, binary input) + LIF + count over t + fused FC.
// Grid: (8 row-strips, 64 batch, 2 co-halves), 128 threads = 4 rows x 32 cols.
// Spike bit -> packed {1.0,1.0} multiplier (sign-extend trick), unpredicated
// FFMA2 so the fma pipe sees exactly one packed op per 2 MACs.
// ---------------------------------------------------------------------------
__global__ __launch_bounds__(128) void k2_conv2(const float* __restrict__ w2,
                                                const float* __restrict__ b2,
                                                const float* __restrict__ wfc) {
    __shared__ uint2 sm_mask[8][6][34];              // [t][strip row + halo][x + halo]
    __shared__ __align__(16) float sm_w[9 * 64 * 8]; // [pos][cin][co8]
    __shared__ float sm_b[8];
    __shared__ float sm_red[4 * 10];

    const int sy  = blockIdx.x;              // row strip (4 rows each)
    const int b   = blockIdx.y;
    const int zc  = blockIdx.z;              // 0/1 -> output channels [0,32) / [32,64)
    const int tid = threadIdx.x;
    const int ry  = tid >> 5;                // row within strip
    const int xc  = tid & 31;

    // Stage spike masks for this (b, strip) incl. halo, all 8 timesteps.
    for (int i = tid; i < 8 * 6 * 34; i += 128) {
        int t = i / 204, rem = i - t * 204;
        int r = rem / 34, xi = rem - r * 34;
        int gy = sy * 4 - 1 + r;
        int gx = xi - 1;
        uint2 v = make_uint2(0u, 0u);
        if (gy >= 0 && gy < 32 && gx >= 0 && gx < 32) {
            const uint2* gm = (const uint2*)g_mask;
            v = gm[(t * 64 + b) * 1024 + gy * 32 + gx];
        }
        sm_mask[t][r][xi] = v;
    }

    float outacc[10];
#pragma unroll
    for (int o = 0; o < 10; o++) outacc[o] = 0.f;

    const int gp = (sy * 4 + ry) * 32 + xc;  // global pixel index

    for (int chunk = 0; chunk < 4; chunk++) {
        const int coBase = zc * 32 + chunk * 8;
        __syncthreads();
        // sm_w[(pos*64+cin)*8 + co8] = w2[(coBase+co8)*576 + cin*9 + pos]
        for (int i = tid; i < 4608; i += 128) {
            int co8 = i / 576;               // coalesced over 'rest'
            int rest = i - co8 * 576;        // = cin*9 + pos
            int cin = rest / 9, pos = rest - cin * 9;
            sm_w[(pos * 64 + cin) * 8 + co8] = w2[(coBase + co8) * 576 + rest];
        }
        if (tid < 8) sm_b[tid] = b2[coBase + tid];
        __syncthreads();

        unsigned long long acc[8][4];        // [t][channel pair], packed f32x2
#pragma unroll
        for (int t = 0; t < 8; t++) {
#pragma unroll
            for (int q = 0; q < 4; q++) acc[t][q] = 0ull;
        }

#pragma unroll 1
        for (int dy = 0; dy < 3; dy++) {
#pragma unroll 1
            for (int dx = 0; dx < 3; dx++) {
                const int pos = dy * 3 + dx;
                unsigned mx[8], my[8];
#pragma unroll
                for (int t = 0; t < 8; t++) {
                    uint2 m = sm_mask[t][ry + dy][xc + dx];
                    mx[t] = m.x; my[t] = m.y;
                }
                const ulonglong2* wp = (const ulonglong2*)sm_w + pos * 64 * 2;

                // cins 0..31 (mx)
#pragma unroll 1
                for (int cg = 0; cg < 4; cg++) {
                    const int kb = 31 - cg * 8;
#pragma unroll
                    for (int u = 0; u < 8; u++) {
                        const int ksh = kb - u;          // shift to move bit to MSB
                        ulonglong2 w01 = wp[(cg * 8 + u) * 2];
                        ulonglong2 w23 = wp[(cg * 8 + u) * 2 + 1];
#pragma unroll
                        for (int t = 0; t < 8; t++) {
                            unsigned sb = ((unsigned)(((int)(mx[t] << ksh)) >> 31))
                                          & 0x3F800000u;
                            unsigned long long s2 =
                                ((unsigned long long)sb << 32) | sb;
                            FFMA4X2(acc[t][0], acc[t][1], acc[t][2], acc[t][3],
                                    w01.x, w01.y, w23.x, w23.y, s2);
                        }
                    }
                }
                // cins 32..63 (my)
#pragma unroll 1
                for (int cg = 0; cg < 4; cg++) {
                    const int kb = 31 - cg * 8;
#pragma unroll
                    for (int u = 0; u < 8; u++) {
                        const int ksh = kb - u;
                        ulonglong2 w01 = wp[(32 + cg * 8 + u) * 2];
                        ulonglong2 w23 = wp[(32 + cg * 8 + u) * 2 + 1];
#pragma unroll
                        for (int t = 0; t < 8; t++) {
                            unsigned sb = ((unsigned)(((int)(my[t] << ksh)) >> 31))
                                          & 0x3F800000u;
                            unsigned long long s2 =
                                ((unsigned long long)sb << 32) | sb;
                            FFMA4X2(acc[t][0], acc[t][1], acc[t][2], acc[t][3],
                                    w01.x, w01.y, w23.x, w23.y, s2);
                        }
                    }
                }
            }
        }

        // threshold -> spike count over t, fold into FC
#pragma unroll
        for (int jp = 0; jp < 4; jp++) {
            const float bias0 = sm_b[jp * 2];
            const float bias1 = sm_b[jp * 2 + 1];
            float cnt0 = 0.f, cnt1 = 0.f;
#pragma unroll
            for (int t = 0; t < 8; t++) {
                float lo, hi;
                asm("mov.b64 {%0,%1}, %2;" : "=f"(lo), "=f"(hi) : "l"(acc[t][jp]));
                cnt0 += ((lo + bias0) >= THR) ? 1.f : 0.f;
                cnt1 += ((hi + bias1) >= THR) ? 1.f : 0.f;
            }
            const int fi0 = (coBase + jp * 2) * 1024 + gp;
            const int fi1 = fi0 + 1024;
#pragma unroll
            for (int o = 0; o < 10; o++)
                outacc[o] += cnt0 * __ldg(&wfc[o * 65536 + fi0])
                           + cnt1 * __ldg(&wfc[o * 65536 + fi1]);
        }
    }

    // block reduction of the 10 partial class sums
    const int lane = tid & 31, wid = tid >> 5;
#pragma unroll
    for (int o = 0; o < 10; o++) {
        float v = outacc[o];
        v += __shfl_down_sync(0xffffffffu, v, 16);
        v += __shfl_down_sync(0xffffffffu, v, 8);
        v += __shfl_down_sync(0xffffffffu, v, 4);
        v += __shfl_down_sync(0xffffffffu, v, 2);
        v += __shfl_down_sync(0xffffffffu, v, 1);
        if (lane == 0) sm_red[wid * 10 + o] = v;
    }
    __syncthreads();
    if (tid < 10) {
        float s = sm_red[tid] + sm_red[10 + tid] + sm_red[20 + tid] + sm_red[30 + tid];
        const int blockLin = (b * 8 + sy) * 2 + zc;  // = b*16 + sy*2 + zc
        g_part[blockLin * 10 + tid] = s;
    }
}

// ---------------------------------------------------------------------------
// Kernel 3: deterministic final reduction: out[b][o] = 8*bfc[o] + sum(parts)
// ---------------------------------------------------------------------------
__global__ void k3_final(const float* __restrict__ bfc, float* __restrict__ out) {
    const int tid = threadIdx.x;
    if (tid < 640) {
        const int b = tid / 10, o = tid - b * 10;
        float s = 8.f * bfc[o];
#pragma unroll
        for (int k = 0; k < 16; k++) s += g_part[(b * 16 + k) * 10 + o];
        out[tid] = s;
    }
}

extern "C" void kernel_launch(void* const* d_in, const int* in_sizes, int n_in,
                              void* d_out, int out_size) {
    const float* x   = (const float*)d_in[0];  // [8,64,3,32,32]
    const float* w1  = (const float*)d_in[1];  // [64,3,3,3]
    const float* b1  = (const float*)d_in[2];  // [64]
    const float* w2  = (const float*)d_in[3];  // [64,64,3,3]
    const float* b2  = (const float*)d_in[4];  // [64]
    const float* wfc = (const float*)d_in[5];  // [10, 65536]
    const float* bfc = (const float*)d_in[6];  // [10]
    float* out = (float*)d_out;                // [64,10]

    k1_conv1<<<512, 256>>>(x, w1, b1);
    k2_conv2<<<dim3(8, 64, 2), 128>>>(w2, b2, wfc);
    k3_final<<<1, 640>>>(bfc, out);
}